// round 12
// baseline (speedup 1.0000x reference)
#include <cuda_runtime.h>
#include <cstdint>

// ---------------- problem constants ----------------
#define C_CH    321
#define D_K     512
#define P_OUT   720
#define N_B     64           // batch == GEMM M
#define BNT     256          // p-cols per CTA (2 panels of 128)
#define BK      16           // k-chunk
#define KCHUNKS (D_K / BK)   // 32
#define NPAIRS  (KCHUNKS / 2)
#define STAGES  5
#define NTHREADS 256

// ---------------- smem layout ----------------
// A: 64 rows x 16 floats (64B rows), XOR-16B swizzle on (r>>1)&3 (ldmatrix-ready).
// B: 2 panels x (16 rows x 136 floats padded).
#define A_STAGE_BYTES  4096
#define B_STRIDE 136
#define B_PANEL_BYTES  (BK * B_STRIDE * 4)        // 8704
#define B_PANEL_FLOATS (B_PANEL_BYTES / 4)        // 2176 (mod 32 == 0: bank-neutral)
#define B_STAGE_BYTES  (2 * B_PANEL_BYTES)        // 17408
#define B_BASE         (STAGES * A_STAGE_BYTES)               // 20480
#define SMEM_BYTES     (B_BASE + STAGES * B_STAGE_BYTES)      // 107520 (105 KB) -> 2 CTAs/SM

// ---------------- helpers ----------------
__device__ __forceinline__ uint32_t smem_to_u32(const void* p) {
    uint32_t a;
    asm("{ .reg .u64 t; cvta.to.shared.u64 t, %1; cvt.u32.u64 %0, t; }" : "=r"(a) : "l"(p));
    return a;
}
// fp32 -> tf32 round-to-nearest via mantissa carry add (HMMA reads top 19 bits).
__device__ __forceinline__ uint32_t rtf32(float f) {
    return __float_as_uint(f) + 0x1000u;
}
#define CP_ASYNC16(dst, src) \
    asm volatile("cp.async.cg.shared.global [%0], [%1], 16;" :: "r"(dst), "l"(src))
#define CP_ASYNC16_Z(dst, src, sz) \
    asm volatile("cp.async.cg.shared.global [%0], [%1], 16, %2;" :: "r"(dst), "l"(src), "r"(sz))
#define CP_COMMIT()  asm volatile("cp.async.commit_group;" ::: "memory")
#define CP_WAIT1()   asm volatile("cp.async.wait_group 1;" ::: "memory")
#define LDMATRIX_X4(r0, r1, r2, r3, addr) \
    asm volatile("ldmatrix.sync.aligned.m8n8.x4.shared.b16 {%0,%1,%2,%3}, [%4];" \
        : "=r"(r0), "=r"(r1), "=r"(r2), "=r"(r3) : "r"(addr))

__device__ __forceinline__ void mma_tf32(float* acc, const uint32_t* a, const uint32_t* b) {
    asm volatile(
        "mma.sync.aligned.m16n8k8.row.col.f32.tf32.tf32.f32 "
        "{%0,%1,%2,%3}, {%4,%5,%6,%7}, {%8,%9}, {%0,%1,%2,%3};"
        : "+f"(acc[0]), "+f"(acc[1]), "+f"(acc[2]), "+f"(acc[3])
        : "r"(a[0]), "r"(a[1]), "r"(a[2]), "r"(a[3]), "r"(b[0]), "r"(b[1]));
}

// ---------------- kernel ----------------
// CTA (blockIdx.x = 256-wide p-slab, blockIdx.y = channel c):
//   out[b, c, p0:p0+256] = x[b, c, :] @ W[c, :, p0:p0+256] + bias
// M=64 x N=256 x K=512 tf32 mma.sync; 8 warps, warp tile 64x32 (16 cols/panel).
// 5-stage cp.async ring of BK=16 chunks, processed in PAIRS: one barrier per 32k,
// two chunks issued before compute (stages +3,+4 mod 5 are disjoint from the pair
// being computed and overwrite the pair finished last iteration).
__global__ void __launch_bounds__(NTHREADS, 2)
pc_linear_mma(const float* __restrict__ x,
              const float* __restrict__ W,
              const float* __restrict__ bias,
              float* __restrict__ out)
{
    extern __shared__ float sm[];
    const uint32_t sbase = smem_to_u32(sm);

    const int tid  = threadIdx.x;
    const int lane = tid & 31;
    const int wid  = tid >> 5;    // warp col (0..7) -> 16 cols per panel
    const int gid  = lane >> 2;   // fragment group id (0..7)
    const int tig  = lane & 3;    // thread in group (0..3)
    const int c    = blockIdx.y;
    const int p0   = blockIdx.x * BNT;

    const float* xc = x + (size_t)c * D_K;
    const float* Wc = W + (size_t)c * ((size_t)D_K * P_OUT);

    // ---- per-lane ldmatrix offsets (A tile; mt adds 1024B = 16 rows) ----
    // 64B rows, swizzle: 16B-chunk ^= (row>>1)&3. Each 8x8 matrix covers all 32 banks.
    uint32_t foff[2];
    {
        const int m0  = (lane & 7) + (lane & 8);
        const int swz = ((m0 >> 1) & 3) * 16;
        const int hi  = (lane >> 4) * 16;
#pragma unroll
        for (int ks = 0; ks < 2; ++ks)
            foff[ks] = (uint32_t)(m0 * 64 + ((ks * 32 + hi) ^ swz));
    }

    // ---- cp.async issue for one K-chunk into one stage ----
    auto issue = [&](int chunk, int stage) {
        const int k0 = chunk * BK;
        // A tile: 64 rows x 16 floats, swizzled (one 16B op per thread)
        const uint32_t abase = sbase + (uint32_t)stage * A_STAGE_BYTES;
        {
            const int r  = tid >> 2;                 // batch row
            const int c4 = tid & 3;                  // 16B chunk
            const int sc = c4 ^ ((r >> 1) & 3);      // swizzled chunk
            const float* src = xc + (size_t)r * (C_CH * D_K) + k0 + c4 * 4;
            CP_ASYNC16(abase + (uint32_t)(r * 64 + sc * 16), src);
        }
        // B: 2 panels x (16 rows x 128 floats, pad 136); zero-fill OOB p
        const uint32_t bbase = sbase + B_BASE + (uint32_t)stage * B_STAGE_BYTES;
#pragma unroll
        for (int j = 0; j < 4; ++j) {
            const int id  = tid + j * NTHREADS;      // 0..1023
            const int t   = id >> 9;                 // panel
            const int rem = id & 511;
            const int r   = rem >> 5;                // k row (0..15)
            const int col = (rem & 31) * 4;          // p offset in panel
            const int pg  = p0 + t * 128 + col;
            const float* src = Wc + (size_t)(k0 + r) * P_OUT + pg;
            const int sz = (pg < P_OUT) ? 16 : 0;
            CP_ASYNC16_Z(bbase + (uint32_t)(t * B_PANEL_BYTES + (r * B_STRIDE + col) * 4), src, sz);
        }
    };

    float acc[4][4][4];   // mt x (panel*2+nt) x quad
#pragma unroll
    for (int mt = 0; mt < 4; ++mt)
#pragma unroll
        for (int n = 0; n < 4; ++n)
#pragma unroll
            for (int q = 0; q < 4; ++q) acc[mt][n][q] = 0.f;

    // ---- compute one landed BK=16 stage ----
    auto compute = [&](int stage) {
        const uint32_t As_b = sbase + (uint32_t)stage * A_STAGE_BYTES;
        const float*   Bs   = sm + (B_BASE / 4) + (size_t)stage * (B_STAGE_BYTES / 4);
#pragma unroll
        for (int ks = 0; ks < 2; ++ks) {
            uint32_t af[4][4], bf[4][2];
            const uint32_t a0 = As_b + foff[ks];
#pragma unroll
            for (int mt = 0; mt < 4; ++mt)
                LDMATRIX_X4(af[mt][0], af[mt][1], af[mt][2], af[mt][3],
                            a0 + (uint32_t)mt * 1024);

            const int kb = ks * 8 + tig;
#pragma unroll
            for (int t = 0; t < 2; ++t)
#pragma unroll
                for (int nt = 0; nt < 2; ++nt) {
                    const int col = t * B_PANEL_FLOATS + wid * 16 + nt * 8 + gid;
                    bf[t * 2 + nt][0] = rtf32(Bs[kb * B_STRIDE + col]);
                    bf[t * 2 + nt][1] = rtf32(Bs[(kb + 4) * B_STRIDE + col]);
                }
#pragma unroll
            for (int mt = 0; mt < 4; ++mt)
#pragma unroll
                for (int n = 0; n < 4; ++n)
                    mma_tf32(acc[mt][n], af[mt], bf[n]);
        }
    };

    // ---- prologue: 3 chunks in flight ----
    issue(0, 0); CP_COMMIT();
    issue(1, 1); CP_COMMIT();
    issue(2, 2); CP_COMMIT();

    // ---- mainloop: one barrier per PAIR of chunks (32 k) ----
    int sa = 0;                  // stage of chunk 2j (advances +2 mod 5)
#pragma unroll 1
    for (int j = 0; j < NPAIRS; ++j) {
        CP_WAIT1();              // chunks 2j, 2j+1 landed (ledger: 3 + 2j commits)
        __syncthreads();         // publish pair; proves previous pair's compute done

        const int ca = 2 * j;
        // issue 2 ahead into stages sa+3, sa+4 (mod 5): disjoint from sa, sa+1
        {
            int s3 = sa + 3; if (s3 >= STAGES) s3 -= STAGES;
            int s4 = sa + 4; if (s4 >= STAGES) s4 -= STAGES;
            if (ca + 3 < KCHUNKS) issue(ca + 3, s3);
            CP_COMMIT();
            if (ca + 4 < KCHUNKS) issue(ca + 4, s4);
            CP_COMMIT();
        }

        int sb = sa + 1; if (sb >= STAGES) sb -= STAGES;
        compute(sa);
        compute(sb);
        sa += 2; if (sa >= STAGES) sa -= STAGES;
    }

    // ---- epilogue: D[b][p] + bias[c][p] -> out[b][c][p] ----
#pragma unroll
    for (int t = 0; t < 2; ++t)
#pragma unroll
        for (int nt = 0; nt < 2; ++nt) {
            const int p = p0 + t * 128 + wid * 16 + nt * 8 + tig * 2;
            if (p < P_OUT) {
                const float2 bv = *(const float2*)(bias + (size_t)c * P_OUT + p);
#pragma unroll
                for (int mt = 0; mt < 4; ++mt) {
                    const int b0r = mt * 16 + gid;
                    const float* a = acc[mt][t * 2 + nt];
                    float2 v0 = make_float2(a[0] + bv.x, a[1] + bv.y);
                    float2 v1 = make_float2(a[2] + bv.x, a[3] + bv.y);
                    *(float2*)(out + ((size_t)b0r * C_CH + c) * P_OUT + p)       = v0;
                    *(float2*)(out + ((size_t)(b0r + 8) * C_CH + c) * P_OUT + p) = v1;
                }
            }
        }
}

// ---------------- launch ----------------
extern "C" void kernel_launch(void* const* d_in, const int* in_sizes, int n_in,
                              void* d_out, int out_size) {
    const float* x  = (const float*)d_in[0];  // [64, 321, 512]
    const float* W  = (const float*)d_in[1];  // [321, 512, 720]
    const float* bi = (const float*)d_in[2];  // [321, 720]
    float* out      = (float*)d_out;          // [64, 321, 720]

    cudaFuncSetAttribute(pc_linear_mma,
                         cudaFuncAttributeMaxDynamicSharedMemorySize, SMEM_BYTES);
    dim3 grid((P_OUT + BNT - 1) / BNT, C_CH);   // 3 x 321 = 963 CTAs
    pc_linear_mma<<<grid, NTHREADS, SMEM_BYTES>>>(x, W, bi, out);
}

// round 13
// speedup vs baseline: 1.0246x; 1.0246x over previous
#include <cuda_runtime.h>
#include <cstdint>

// ---------------- problem constants ----------------
#define C_CH    321
#define D_K     512
#define P_OUT   720
#define N_B     64           // batch == GEMM M
#define BN      128          // p-tile == GEMM N
#define BK      16           // k-chunk
#define KCHUNKS (D_K / BK)   // 32
#define NPAIRS  (KCHUNKS / 2)
#define STAGES  4
#define NTHREADS 256

// ---------------- smem layout ----------------
// A: 64 rows x 16 floats (64B rows), XOR-16B swizzle on (r>>1)&3 (ldmatrix-ready).
// B: 16 rows x 136 floats (padded, conflict-free scalar LDS).
#define A_STAGE_BYTES  4096
#define B_STRIDE 136
#define B_STAGE_BYTES  (BK * B_STRIDE * 4)   // 8704
#define B_BASE         (STAGES * A_STAGE_BYTES)            // 16384
#define SMEM_BYTES     (B_BASE + STAGES * B_STAGE_BYTES)   // 51200 (50 KB) -> 4 CTAs/SM

// ---------------- helpers ----------------
__device__ __forceinline__ uint32_t smem_to_u32(const void* p) {
    uint32_t a;
    asm("{ .reg .u64 t; cvta.to.shared.u64 t, %1; cvt.u32.u64 %0, t; }" : "=r"(a) : "l"(p));
    return a;
}
// fp32 -> tf32 round-to-nearest via mantissa carry add (HMMA reads top 19 bits).
__device__ __forceinline__ uint32_t rtf32(float f) {
    return __float_as_uint(f) + 0x1000u;
}
#define CP_ASYNC16(dst, src) \
    asm volatile("cp.async.cg.shared.global [%0], [%1], 16;" :: "r"(dst), "l"(src))
#define CP_ASYNC16_Z(dst, src, sz) \
    asm volatile("cp.async.cg.shared.global [%0], [%1], 16, %2;" :: "r"(dst), "l"(src), "r"(sz))
#define CP_COMMIT()  asm volatile("cp.async.commit_group;" ::: "memory")
#define CP_WAIT0()   asm volatile("cp.async.wait_group 0;" ::: "memory")
#define LDMATRIX_X4(r0, r1, r2, r3, addr) \
    asm volatile("ldmatrix.sync.aligned.m8n8.x4.shared.b16 {%0,%1,%2,%3}, [%4];" \
        : "=r"(r0), "=r"(r1), "=r"(r2), "=r"(r3) : "r"(addr))

__device__ __forceinline__ void mma_tf32(float* acc, const uint32_t* a, const uint32_t* b) {
    asm volatile(
        "mma.sync.aligned.m16n8k8.row.col.f32.tf32.tf32.f32 "
        "{%0,%1,%2,%3}, {%4,%5,%6,%7}, {%8,%9}, {%0,%1,%2,%3};"
        : "+f"(acc[0]), "+f"(acc[1]), "+f"(acc[2]), "+f"(acc[3])
        : "r"(a[0]), "r"(a[1]), "r"(a[2]), "r"(a[3]), "r"(b[0]), "r"(b[1]));
}

// ---------------- kernel ----------------
// CTA (blockIdx.x = p-tile, blockIdx.y = channel c):
//   out[b, c, p0:p0+128] = x[b, c, :] @ W[c, :, p0:p0+128] + bias[c, p0:p0+128]
// M=64 x N=128 x K=512 tf32 mma.sync; 8 warps in 1x8 grid (warp tile 64x16).
// BK=16 chunks in a 4-stage cp.async ring, processed in PAIRS (1 barrier per 32k):
// each iter issues the NEXT pair into the two stages disjoint from the pair being
// computed. 4 CTAs/SM (50 KB smem, 64-reg cap).
__global__ void __launch_bounds__(NTHREADS, 4)
pc_linear_mma(const float* __restrict__ x,
              const float* __restrict__ W,
              const float* __restrict__ bias,
              float* __restrict__ out)
{
    extern __shared__ float sm[];
    const uint32_t sbase = smem_to_u32(sm);

    const int tid  = threadIdx.x;
    const int lane = tid & 31;
    const int wid  = tid >> 5;    // warp col (0..7) -> n0 = wid*16
    const int gid  = lane >> 2;   // fragment group id (0..7)
    const int tig  = lane & 3;    // thread in group (0..3)
    const int c    = blockIdx.y;
    const int p0   = blockIdx.x * BN;

    const float* xc = x + (size_t)c * D_K;
    const float* Wc = W + (size_t)c * ((size_t)D_K * P_OUT);

    // ---- per-lane ldmatrix offsets (A tile; mt adds 1024B = 16 rows) ----
    // 64B rows, swizzle: 16B-chunk ^= (row>>1)&3. Each 8x8 matrix covers all 32 banks.
    uint32_t foff[2];
    {
        const int m0  = (lane & 7) + (lane & 8);
        const int swz = ((m0 >> 1) & 3) * 16;
        const int hi  = (lane >> 4) * 16;
#pragma unroll
        for (int ks = 0; ks < 2; ++ks)
            foff[ks] = (uint32_t)(m0 * 64 + ((ks * 32 + hi) ^ swz));
    }

    // ---- cp.async issue for one K-chunk into one stage ----
    auto issue = [&](int chunk, int stage) {
        const int k0 = chunk * BK;
        // A tile: 64 rows x 16 floats, swizzled (one 16B op per thread)
        const uint32_t abase = sbase + (uint32_t)stage * A_STAGE_BYTES;
        {
            const int r  = tid >> 2;                 // batch row
            const int c4 = tid & 3;                  // 16B chunk
            const int sc = c4 ^ ((r >> 1) & 3);      // swizzled chunk
            const float* src = xc + (size_t)r * (C_CH * D_K) + k0 + c4 * 4;
            CP_ASYNC16(abase + (uint32_t)(r * 64 + sc * 16), src);
        }
        // B tile: 16 rows x 128 floats (pad 136); zero-fill OOB p
        const uint32_t bbase = sbase + B_BASE + (uint32_t)stage * B_STAGE_BYTES;
#pragma unroll
        for (int j = 0; j < 2; ++j) {
            const int id  = tid + j * NTHREADS;
            const int r   = id >> 5;          // k row (0..15)
            const int col = (id & 31) * 4;    // p offset
            const float* src = Wc + (size_t)(k0 + r) * P_OUT + p0 + col;
            const int sz = (p0 + col < P_OUT) ? 16 : 0;
            CP_ASYNC16_Z(bbase + (uint32_t)(r * B_STRIDE + col) * 4, src, sz);
        }
    };

    float acc[4][2][4];   // mt x nt x quad (32 regs)
#pragma unroll
    for (int mt = 0; mt < 4; ++mt)
#pragma unroll
        for (int nt = 0; nt < 2; ++nt)
#pragma unroll
            for (int q = 0; q < 4; ++q) acc[mt][nt][q] = 0.f;

    // ---- compute one landed BK=16 stage ----
    auto compute = [&](int stage) {
        const uint32_t As_b = sbase + (uint32_t)stage * A_STAGE_BYTES;
        const float*   Bs   = sm + (B_BASE / 4) + (size_t)stage * (B_STAGE_BYTES / 4);
#pragma unroll
        for (int ks = 0; ks < 2; ++ks) {
            uint32_t af[4][4], bf[2][2];
            const uint32_t a0 = As_b + foff[ks];
#pragma unroll
            for (int mt = 0; mt < 4; ++mt)
                LDMATRIX_X4(af[mt][0], af[mt][1], af[mt][2], af[mt][3],
                            a0 + (uint32_t)mt * 1024);

            const int kb = ks * 8 + tig;
#pragma unroll
            for (int nt = 0; nt < 2; ++nt) {
                const int col = wid * 16 + nt * 8 + gid;
                bf[nt][0] = rtf32(Bs[kb * B_STRIDE + col]);
                bf[nt][1] = rtf32(Bs[(kb + 4) * B_STRIDE + col]);
            }
#pragma unroll
            for (int mt = 0; mt < 4; ++mt)
#pragma unroll
                for (int nt = 0; nt < 2; ++nt)
                    mma_tf32(acc[mt][nt], af[mt], bf[nt]);
        }
    };

    // ---- prologue: first pair in flight ----
    issue(0, 0); CP_COMMIT();
    issue(1, 1); CP_COMMIT();

    // ---- mainloop: one barrier per PAIR of chunks (32 k) ----
#pragma unroll 1
    for (int j = 0; j < NPAIRS; ++j) {
        const int ca = 2 * j;
        CP_WAIT0();              // chunks <= 2j+1 landed (all committed groups)
        __syncthreads();         // publish pair; proves previous pair's compute done

        // issue next pair into the two stages disjoint from (2j)&3, (2j+1)&3
        if (ca + 2 < KCHUNKS) { issue(ca + 2, (ca + 2) & 3); }
        CP_COMMIT();
        if (ca + 3 < KCHUNKS) { issue(ca + 3, (ca + 3) & 3); }
        CP_COMMIT();

        compute(ca & 3);
        compute((ca + 1) & 3);
    }

    // ---- epilogue: D[b][p] + bias[c][p] -> out[b][c][p] ----
#pragma unroll
    for (int nt = 0; nt < 2; ++nt) {
        const int p = p0 + wid * 16 + nt * 8 + tig * 2;
        if (p < P_OUT) {
            const float2 bv = *(const float2*)(bias + (size_t)c * P_OUT + p);
#pragma unroll
            for (int mt = 0; mt < 4; ++mt) {
                const int b0r = mt * 16 + gid;
                const float* a = acc[mt][nt];
                float2 v0 = make_float2(a[0] + bv.x, a[1] + bv.y);
                float2 v1 = make_float2(a[2] + bv.x, a[3] + bv.y);
                *(float2*)(out + ((size_t)b0r * C_CH + c) * P_OUT + p)       = v0;
                *(float2*)(out + ((size_t)(b0r + 8) * C_CH + c) * P_OUT + p) = v1;
            }
        }
    }
}

// ---------------- launch ----------------
extern "C" void kernel_launch(void* const* d_in, const int* in_sizes, int n_in,
                              void* d_out, int out_size) {
    const float* x  = (const float*)d_in[0];  // [64, 321, 512]
    const float* W  = (const float*)d_in[1];  // [321, 512, 720]
    const float* bi = (const float*)d_in[2];  // [321, 720]
    float* out      = (float*)d_out;          // [64, 321, 720]

    cudaFuncSetAttribute(pc_linear_mma,
                         cudaFuncAttributeMaxDynamicSharedMemorySize, SMEM_BYTES);
    dim3 grid((P_OUT + BN - 1) / BN, C_CH);   // 6 x 321 = 1926 CTAs
    pc_linear_mma<<<grid, NTHREADS, SMEM_BYTES>>>(x, W, bi, out);
}